// round 7
// baseline (speedup 1.0000x reference)
#include <cuda_runtime.h>
#include <cuda_bf16.h>
#include <cstdint>

#define L_HOPS 5
#define D_DIM  32
#define E_MAX  131072
#define BLOCK  256

// Precomputed dots[e][l] = <edge_vector[l], edge_attr[e]>  (2.6 MB, L2-resident)
__device__ float g_table[(size_t)E_MAX * L_HOPS];

// 1/max(len,1); len==0 -> 0 (sum is 0 anyway)
__constant__ float c_inv[8] = {0.0f, 1.0f, 0.5f, 1.0f / 3.0f, 0.25f, 0.2f, 0.0f, 0.0f};

// ---------------------------------------------------------------------------
// Kernel 1: per-(edge, hop) dot products. One thread per edge (128 B row).
// ---------------------------------------------------------------------------
__global__ void __launch_bounds__(256) precompute_dots_kernel(
    const float* __restrict__ edge_attr,   // [E, 32]
    const float* __restrict__ edge_vector, // [5, 32]
    int E)
{
    __shared__ float sev[L_HOPS * D_DIM];
    if (threadIdx.x < L_HOPS * D_DIM)
        sev[threadIdx.x] = edge_vector[threadIdx.x];
    __syncthreads();

    int e = blockIdx.x * blockDim.x + threadIdx.x;
    if (e >= E) return;

    const float4* row = reinterpret_cast<const float4*>(edge_attr + (size_t)e * D_DIM);

    float acc0 = 0.f, acc1 = 0.f, acc2 = 0.f, acc3 = 0.f, acc4 = 0.f;
#pragma unroll
    for (int i = 0; i < D_DIM / 4; i++) {
        float4 v = row[i];
#pragma unroll
        for (int c = 0; c < 4; c++) {
            float a = (c == 0) ? v.x : (c == 1) ? v.y : (c == 2) ? v.z : v.w;
            int d = i * 4 + c;
            acc0 = fmaf(a, sev[0 * D_DIM + d], acc0);
            acc1 = fmaf(a, sev[1 * D_DIM + d], acc1);
            acc2 = fmaf(a, sev[2 * D_DIM + d], acc2);
            acc3 = fmaf(a, sev[3 * D_DIM + d], acc3);
            acc4 = fmaf(a, sev[4 * D_DIM + d], acc4);
        }
    }

    float* t = g_table + (size_t)e * L_HOPS;
    t[0] = acc0; t[1] = acc1; t[2] = acc2; t[3] = acc3; t[4] = acc4;
}

// ---------------------------------------------------------------------------
// Kernel 2: 1 pair/thread with LANE-GROUP SPLIT gathers.
// Each gather is issued as 4 predicated copies (one per lane quarter) into
// distinct registers: 8 active lanes per LDG -> 8 wavefronts/instruction
// (vs 32), exploiting the ~1.0 cyc/wf cross-LDG rate instead of the
// ~2.07 cyc/wf within-LDG replay rate. Index stream staged via smem
// (coalesced int4 in; stride-5 scalar LDS out is bank-conflict-free).
// ---------------------------------------------------------------------------
__global__ void __launch_bounds__(BLOCK) pair_reduce_lanesplit(
    const int* __restrict__ path_edges,  // [P, 5]
    const int* __restrict__ path_len,    // [P]
    float* __restrict__ out,             // [P]
    int P)
{
    __shared__ int s_idx[BLOCK * L_HOPS];

    int tid  = threadIdx.x;
    int base = blockIdx.x * BLOCK;

    // Coalesced stage of this block's 256*5 indices (320 int4).
    {
        const int4* gpe = reinterpret_cast<const int4*>(path_edges)
                        + ((size_t)base * L_HOPS) / 4;
        int4* s4 = reinterpret_cast<int4*>(s_idx);
        int total_vec = (int)(((size_t)P * L_HOPS) / 4 - ((size_t)base * L_HOPS) / 4);
#pragma unroll
        for (int k = 0; k < (BLOCK * L_HOPS / 4 + BLOCK - 1) / BLOCK; k++) {
            int i = tid + k * BLOCK;
            if (i < BLOCK * L_HOPS / 4 && i < total_vec)
                s4[i] = __ldg(gpe + i);
        }
    }
    __syncthreads();

    int p = base + tid;
    if (p >= P) return;

    // Conflict-free readback (stride 5 coprime with 32 banks).
    unsigned i0 = (unsigned)s_idx[tid * 5 + 0];
    unsigned i1 = (unsigned)s_idx[tid * 5 + 1];
    unsigned i2 = (unsigned)s_idx[tid * 5 + 2];
    unsigned i3 = (unsigned)s_idx[tid * 5 + 3];
    unsigned i4 = (unsigned)s_idx[tid * 5 + 4];

    int len = __ldg(path_len + p);
    int grp = (tid >> 3) & 3;   // lane quarter

    // 4 predicated copies of each gather, distinct destination registers.
    float t0[L_HOPS], t1[L_HOPS], t2[L_HOPS], t3[L_HOPS];
    {
        bool a = (grp == 0);
        t0[0] = (a && len > 0) ? __ldg(&g_table[i0 * 5u + 0u]) : 0.f;
        t0[1] = (a && len > 1) ? __ldg(&g_table[i1 * 5u + 1u]) : 0.f;
        t0[2] = (a && len > 2) ? __ldg(&g_table[i2 * 5u + 2u]) : 0.f;
        t0[3] = (a && len > 3) ? __ldg(&g_table[i3 * 5u + 3u]) : 0.f;
        t0[4] = (a && len > 4) ? __ldg(&g_table[i4 * 5u + 4u]) : 0.f;
    }
    {
        bool a = (grp == 1);
        t1[0] = (a && len > 0) ? __ldg(&g_table[i0 * 5u + 0u]) : 0.f;
        t1[1] = (a && len > 1) ? __ldg(&g_table[i1 * 5u + 1u]) : 0.f;
        t1[2] = (a && len > 2) ? __ldg(&g_table[i2 * 5u + 2u]) : 0.f;
        t1[3] = (a && len > 3) ? __ldg(&g_table[i3 * 5u + 3u]) : 0.f;
        t1[4] = (a && len > 4) ? __ldg(&g_table[i4 * 5u + 4u]) : 0.f;
    }
    {
        bool a = (grp == 2);
        t2[0] = (a && len > 0) ? __ldg(&g_table[i0 * 5u + 0u]) : 0.f;
        t2[1] = (a && len > 1) ? __ldg(&g_table[i1 * 5u + 1u]) : 0.f;
        t2[2] = (a && len > 2) ? __ldg(&g_table[i2 * 5u + 2u]) : 0.f;
        t2[3] = (a && len > 3) ? __ldg(&g_table[i3 * 5u + 3u]) : 0.f;
        t2[4] = (a && len > 4) ? __ldg(&g_table[i4 * 5u + 4u]) : 0.f;
    }
    {
        bool a = (grp == 3);
        t3[0] = (a && len > 0) ? __ldg(&g_table[i0 * 5u + 0u]) : 0.f;
        t3[1] = (a && len > 1) ? __ldg(&g_table[i1 * 5u + 1u]) : 0.f;
        t3[2] = (a && len > 2) ? __ldg(&g_table[i2 * 5u + 2u]) : 0.f;
        t3[3] = (a && len > 3) ? __ldg(&g_table[i3 * 5u + 3u]) : 0.f;
        t3[4] = (a && len > 4) ? __ldg(&g_table[i4 * 5u + 4u]) : 0.f;
    }

    // Exactly one group per thread contributed non-zeros.
    float s = 0.f;
#pragma unroll
    for (int l = 0; l < L_HOPS; l++)
        s += (t0[l] + t1[l]) + (t2[l] + t3[l]);

    out[p] = s * c_inv[len & 7];
}

// ---------------------------------------------------------------------------
// Inputs: x[N,32], edge_attr[E,32], edge_vector[5,32],
//         path_edges[P,5] (int32), path_len[P] (int32)  -> out float32 [P]
// ---------------------------------------------------------------------------
extern "C" void kernel_launch(void* const* d_in, const int* in_sizes, int n_in,
                              void* d_out, int out_size)
{
    const float* edge_attr   = (const float*)d_in[1];
    const float* edge_vector = (const float*)d_in[2];
    const int*   path_edges  = (const int*)d_in[3];
    const int*   path_len    = (const int*)d_in[4];
    float*       out         = (float*)d_out;

    int E = in_sizes[1] / D_DIM;
    int P = out_size;

    {
        int threads = 256;
        int blocks = (E + threads - 1) / threads;
        precompute_dots_kernel<<<blocks, threads>>>(edge_attr, edge_vector, E);
    }
    {
        int blocks = (P + BLOCK - 1) / BLOCK;
        pair_reduce_lanesplit<<<blocks, BLOCK>>>(path_edges, path_len, out, P);
    }
}